// round 1
// baseline (speedup 1.0000x reference)
#include <cuda_runtime.h>
#include <cuda_bf16.h>
#include <cstdint>

// Problem constants
#define BATCH   16
#define NTOK    4096
#define CDIM    256
#define WS      8
#define NH      8
#define HD      32
#define LK      32
#define GB      16          // global bank tokens
#define HSIDE   64          // sqrt(N)
#define NWSIDE  8           // windows per side
#define NW      64          // tokens per window (WS*WS)
#define BW      1024        // total windows (B * 8 * 8)
#define MROWS   65536       // BW * NW
#define NKEY    48          // LK + GB

// ---------------- scratch (device globals; no allocation allowed) ----------------
__device__ float g_q[BW * NH * NW * HD];   // [w][h][t][d]
__device__ float g_k[BW * NH * NW * HD];
__device__ float g_v[BW * NH * NW * HD];
__device__ float g_ao[MROWS * CDIM];       // attention output, window-major rows

// =================================================================================
// Kernel 1: QKV GEMM fused with window partition.
//   M = 65536 rows in WINDOW ORDER (block x = window), K = 256, N = 768.
//   A rows gathered from x via window mapping; C scattered into g_q/g_k/g_v
//   in [w][h][t][d] layout.
// =================================================================================
#define BM 64
#define BN 64
#define BK 16

__global__ void __launch_bounds__(256) qkv_kernel(const float* __restrict__ x,
                                                  const float* __restrict__ Wqkv,
                                                  const float* __restrict__ bqkv)
{
    __shared__ float As[BM][BK + 1];
    __shared__ float Bs[BK][BN];

    const int w  = blockIdx.x;          // window id (rows w*64 .. w*64+63)
    const int n0 = blockIdx.y * BN;     // output-col tile base (0..704)
    const int tid = threadIdx.x;

    // ---- A-load mapping: thread -> (row ar in window, 4 cols at ac)
    const int ar = tid >> 2;            // 0..63 (token within window)
    const int ac = (tid & 3) * 4;       // 0,4,8,12
    {
        // nothing: row pointer computed below
    }
    const int b    = w >> 6;
    const int wrem = w & 63;
    const int wy   = wrem >> 3;
    const int wx   = wrem & 7;
    const int tyy  = ar >> 3;
    const int txx  = ar & 7;
    const int gtok = ((wy * 8 + tyy) << 6) + (wx * 8 + txx);    // global token index
    const float* xrow = x + (size_t)(b * NTOK + gtok) * CDIM;

    // ---- B-load mapping
    const int br = tid >> 4;            // 0..15
    const int bc = (tid & 15) * 4;      // 0..60

    // ---- compute mapping: 16x16 threads, 4x4 microtile each
    const int cty = tid >> 4;           // 0..15
    const int ctx = tid & 15;           // 0..15

    float acc[4][4] = {};

    for (int k0 = 0; k0 < CDIM; k0 += BK) {
        float4 av = *(const float4*)(xrow + k0 + ac);
        As[ar][ac + 0] = av.x;
        As[ar][ac + 1] = av.y;
        As[ar][ac + 2] = av.z;
        As[ar][ac + 3] = av.w;
        float4 bv = *(const float4*)(Wqkv + (size_t)(k0 + br) * 768 + n0 + bc);
        *(float4*)&Bs[br][bc] = bv;
        __syncthreads();

        #pragma unroll
        for (int kk = 0; kk < BK; kk++) {
            float a[4];
            #pragma unroll
            for (int i = 0; i < 4; i++) a[i] = As[cty * 4 + i][kk];
            float4 b4 = *(const float4*)&Bs[kk][ctx * 4];
            float bb[4] = {b4.x, b4.y, b4.z, b4.w};
            #pragma unroll
            for (int i = 0; i < 4; i++)
                #pragma unroll
                for (int j = 0; j < 4; j++)
                    acc[i][j] += a[i] * bb[j];
        }
        __syncthreads();
    }

    // ---- writeback scattered into q/k/v [w][h][t][d]
    const int s = n0 >> 8;              // 0=q, 1=k, 2=v (tile never crosses)
    float* dst = (s == 0) ? g_q : ((s == 1) ? g_k : g_v);
    #pragma unroll
    for (int i = 0; i < 4; i++) {
        const int tt = cty * 4 + i;     // token in window
        #pragma unroll
        for (int j = 0; j < 4; j++) {
            const int jg  = n0 + ctx * 4 + j;   // 0..767
            const int rem = jg & 255;
            const int h   = rem >> 5;
            const int d   = rem & 31;
            dst[(((size_t)(w * NH + h) * NW + tt) << 5) + d] = acc[i][j] + bqkv[jg];
        }
    }
}

// =================================================================================
// Kernel 2: per-(window,head) attention. 64 threads = one per query token.
//   - K tile -> smem, compress with E_k (smem), append bank rows -> sKc[48][32]
//   - same for V -> sVc
//   - online softmax WITHOUT max subtraction (scores are O(1); exp cannot overflow)
// =================================================================================
__global__ void __launch_bounds__(64) attn_kernel(const float* __restrict__ E_k,
                                                  const float* __restrict__ E_v,
                                                  const float* __restrict__ k_bank,
                                                  const float* __restrict__ v_bank)
{
    __shared__ float sKV[NW * HD];      // raw k (then v) tile: 64x32
    __shared__ float sE [NW * LK];      // E_k (then E_v): 64x32
    __shared__ float sKc[NKEY * HD];    // compressed+bank keys: 48x32
    __shared__ float sVc[NKEY * HD];

    const int blk = blockIdx.x;         // w*8 + h
    const int w   = blk >> 3;
    const int h   = blk & 7;
    const int tid = threadIdx.x;        // 0..63
    const size_t base = (size_t)blk * NW * HD;

    // ---------- phase 1: K ----------
    {
        const float4* src = (const float4*)(g_k + base + tid * HD);
        float4* dstp = (float4*)(sKV + tid * HD);
        #pragma unroll
        for (int i = 0; i < 8; i++) dstp[i] = src[i];
        const float4* esrc = (const float4*)(E_k) + tid * 8;
        float4* edst = (float4*)(sE) + tid * 8;
        #pragma unroll
        for (int i = 0; i < 8; i++) edst[i] = esrc[i];
    }
    __syncthreads();

    for (int i = 0; i < 16; i++) {              // 1024 compressed outputs
        const int idx = tid + i * 64;
        const int l = idx >> 5, d = idx & 31;
        float sum = 0.f;
        #pragma unroll 16
        for (int nn = 0; nn < NW; nn++)
            sum += sE[nn * LK + l] * sKV[nn * HD + d];
        sKc[idx] = sum;
    }
    #pragma unroll
    for (int i = 0; i < 8; i++) {               // 512 bank entries
        const int idx = tid + i * 64;
        const int g = idx >> 5, d = idx & 31;
        sKc[LK * HD + idx] = __ldg(k_bank + g * CDIM + h * HD + d);
    }
    __syncthreads();

    // ---------- phase 2: V (reuse sKV / sE) ----------
    {
        const float4* src = (const float4*)(g_v + base + tid * HD);
        float4* dstp = (float4*)(sKV + tid * HD);
        #pragma unroll
        for (int i = 0; i < 8; i++) dstp[i] = src[i];
        const float4* esrc = (const float4*)(E_v) + tid * 8;
        float4* edst = (float4*)(sE) + tid * 8;
        #pragma unroll
        for (int i = 0; i < 8; i++) edst[i] = esrc[i];
    }
    __syncthreads();

    for (int i = 0; i < 16; i++) {
        const int idx = tid + i * 64;
        const int l = idx >> 5, d = idx & 31;
        float sum = 0.f;
        #pragma unroll 16
        for (int nn = 0; nn < NW; nn++)
            sum += sE[nn * LK + l] * sKV[nn * HD + d];
        sVc[idx] = sum;
    }
    #pragma unroll
    for (int i = 0; i < 8; i++) {
        const int idx = tid + i * 64;
        const int g = idx >> 5, d = idx & 31;
        sVc[LK * HD + idx] = __ldg(v_bank + g * CDIM + h * HD + d);
    }
    __syncthreads();

    // ---------- phase 3: attention for query token = tid ----------
    float qr[HD];
    {
        const float4* qsrc = (const float4*)(g_q + base + tid * HD);
        #pragma unroll
        for (int i = 0; i < 8; i++) {
            float4 v4 = qsrc[i];
            qr[i * 4 + 0] = v4.x; qr[i * 4 + 1] = v4.y;
            qr[i * 4 + 2] = v4.z; qr[i * 4 + 3] = v4.w;
        }
    }

    const float scale = 0.17677669529663687f;   // 1/sqrt(32)
    float out[HD];
    #pragma unroll
    for (int d = 0; d < HD; d++) out[d] = 0.f;
    float denom = 0.f;

    for (int j = 0; j < NKEY; j++) {
        float sc = 0.f;
        #pragma unroll
        for (int d = 0; d < HD; d++) sc += qr[d] * sKc[j * HD + d];
        const float e = __expf(sc * scale);
        denom += e;
        #pragma unroll
        for (int d = 0; d < HD; d++) out[d] += e * sVc[j * HD + d];
    }
    const float inv = 1.f / denom;

    float* dstrow = g_ao + ((size_t)(w * NW + tid)) * CDIM + h * HD;
    #pragma unroll
    for (int d = 0; d < HD; d += 4) {
        float4 o4 = make_float4(out[d] * inv, out[d + 1] * inv,
                                out[d + 2] * inv, out[d + 3] * inv);
        *(float4*)(dstrow + d) = o4;
    }
}

// =================================================================================
// Kernel 3: projection GEMM fused with window-reverse scatter + bias.
//   M = 65536 (window-major rows of g_ao), K = 256, N = 256.
// =================================================================================
__global__ void __launch_bounds__(256) proj_kernel(const float* __restrict__ Wp,
                                                   const float* __restrict__ bp,
                                                   float* __restrict__ out)
{
    __shared__ float As[BM][BK + 1];
    __shared__ float Bs[BK][BN];

    const int w  = blockIdx.x;          // window id
    const int n0 = blockIdx.y * BN;
    const int tid = threadIdx.x;

    const int ar = tid >> 2;
    const int ac = (tid & 3) * 4;
    const float* arow = g_ao + (size_t)(w * NW + ar) * CDIM;

    const int br = tid >> 4;
    const int bc = (tid & 15) * 4;

    const int cty = tid >> 4;
    const int ctx = tid & 15;

    float acc[4][4] = {};

    for (int k0 = 0; k0 < CDIM; k0 += BK) {
        float4 av = *(const float4*)(arow + k0 + ac);
        As[ar][ac + 0] = av.x;
        As[ar][ac + 1] = av.y;
        As[ar][ac + 2] = av.z;
        As[ar][ac + 3] = av.w;
        float4 bv = *(const float4*)(Wp + (size_t)(k0 + br) * CDIM + n0 + bc);
        *(float4*)&Bs[br][bc] = bv;
        __syncthreads();

        #pragma unroll
        for (int kk = 0; kk < BK; kk++) {
            float a[4];
            #pragma unroll
            for (int i = 0; i < 4; i++) a[i] = As[cty * 4 + i][kk];
            float4 b4 = *(const float4*)&Bs[kk][ctx * 4];
            float bb[4] = {b4.x, b4.y, b4.z, b4.w};
            #pragma unroll
            for (int i = 0; i < 4; i++)
                #pragma unroll
                for (int j = 0; j < 4; j++)
                    acc[i][j] += a[i] * bb[j];
        }
        __syncthreads();
    }

    // window reverse: token (ty,tx) of window (b,wy,wx) -> global n
    const int b    = w >> 6;
    const int wrem = w & 63;
    const int wy   = wrem >> 3;
    const int wx   = wrem & 7;

    #pragma unroll
    for (int i = 0; i < 4; i++) {
        const int tt  = cty * 4 + i;
        const int tyy = tt >> 3;
        const int txx = tt & 7;
        const int gtok = ((wy * 8 + tyy) << 6) + (wx * 8 + txx);
        float* orow = out + (size_t)(b * NTOK + gtok) * CDIM;
        #pragma unroll
        for (int j = 0; j < 4; j++) {
            const int jg = n0 + ctx * 4 + j;
            orow[jg] = acc[i][j] + bp[jg];
        }
    }
}

// =================================================================================
extern "C" void kernel_launch(void* const* d_in, const int* in_sizes, int n_in,
                              void* d_out, int out_size)
{
    (void)in_sizes; (void)n_in; (void)out_size;
    const float* x     = (const float*)d_in[0];
    const float* Wqkv  = (const float*)d_in[1];
    const float* bqkv  = (const float*)d_in[2];
    const float* E_k   = (const float*)d_in[3];
    const float* E_v   = (const float*)d_in[4];
    const float* kbank = (const float*)d_in[5];
    const float* vbank = (const float*)d_in[6];
    const float* Wp    = (const float*)d_in[7];
    const float* bp    = (const float*)d_in[8];
    float* out = (float*)d_out;

    qkv_kernel<<<dim3(BW, 768 / BN), 256>>>(x, Wqkv, bqkv);
    attn_kernel<<<BW * NH, 64>>>(E_k, E_v, kbank, vbank);
    proj_kernel<<<dim3(BW, CDIM / BN), 256>>>(Wp, bp, out);
}

// round 2
// speedup vs baseline: 1.2565x; 1.2565x over previous
#include <cuda_runtime.h>
#include <cuda_bf16.h>
#include <cstdint>

// Problem constants
#define BATCH   16
#define NTOK    4096
#define CDIM    256
#define NH      8
#define HD      32
#define LK      32
#define GB      16
#define NW      64          // tokens per window
#define BW      1024        // total windows
#define MROWS   65536       // BW * NW
#define NKEY    48          // LK + GB

typedef unsigned long long u64;

// ---------------- scratch (device globals; no allocation allowed) ----------------
__device__ __align__(16) float g_q[BW * NH * NW * HD];   // [w][h][t][d]
__device__ __align__(16) float g_k[BW * NH * NW * HD];
__device__ __align__(16) float g_v[BW * NH * NW * HD];
__device__ __align__(16) float g_ao[(size_t)MROWS * CDIM];  // attention out, window-major rows

// ---------------- f32x2 packed-FMA helpers (FFMA2 path, sm_100+) ----------------
__device__ __forceinline__ u64 pack2(float lo, float hi) {
    u64 d;
    asm("mov.b64 %0, {%1, %2};" : "=l"(d)
        : "r"(__float_as_uint(lo)), "r"(__float_as_uint(hi)));
    return d;
}
__device__ __forceinline__ void unpack2(u64 v, float& lo, float& hi) {
    unsigned int a, b;
    asm("mov.b64 {%0, %1}, %2;" : "=r"(a), "=r"(b) : "l"(v));
    lo = __uint_as_float(a);
    hi = __uint_as_float(b);
}
__device__ __forceinline__ void fma2(u64& acc, u64 a, u64 b) {
    asm("fma.rn.f32x2 %0, %1, %2, %0;" : "+l"(acc) : "l"(a), "l"(b));
}

// =================================================================================
// Kernel 1: QKV GEMM (window-major rows) fused with window partition + head scatter
//   BM=128, BN=128, BK=16, 256 threads, 8x8 microtile via f32x2.
// =================================================================================
__global__ void __launch_bounds__(256) qkv_kernel(const float* __restrict__ x,
                                                  const float* __restrict__ Wqkv,
                                                  const float* __restrict__ bqkv)
{
    __shared__ __align__(16) float As[16][128];   // [k][row]
    __shared__ __align__(16) float Bs[16][128];   // [k][col]

    const int tid = threadIdx.x;
    const int bx  = blockIdx.x;
    const int n0  = blockIdx.y * 128;

    // ---- A load ids: each thread loads 8 consecutive k of one row
    const int a_r = tid >> 1;           // 0..127
    const int a_c = (tid & 1) * 8;      // 0 or 8
    // window-major row -> global token gather
    const int r_in  = bx * 128 + a_r;
    const int w_in  = r_in >> 6;
    const int t_in  = r_in & 63;
    const int b_in  = w_in >> 6;
    const int wrem  = w_in & 63;
    const int gtok  = (((wrem >> 3) * 8 + (t_in >> 3)) << 6) + ((wrem & 7) * 8 + (t_in & 7));
    const float* xrow = x + (size_t)(b_in * NTOK + gtok) * CDIM;

    // ---- B load ids
    const int b_r = tid >> 4;           // 0..15
    const int b_c = (tid & 15) * 8;     // 0..120

    // ---- compute ids
    const int ty = tid >> 4, tx = tid & 15;
    const int i0 = ty * 8, j0 = tx * 8;

    u64 acc[4][8] = {};                 // row-pairs (2i,2i+1) x 8 cols

    for (int k0 = 0; k0 < CDIM; k0 += 16) {
        float4 av0 = *(const float4*)(xrow + k0 + a_c);
        float4 av1 = *(const float4*)(xrow + k0 + a_c + 4);
        As[a_c + 0][a_r] = av0.x;  As[a_c + 1][a_r] = av0.y;
        As[a_c + 2][a_r] = av0.z;  As[a_c + 3][a_r] = av0.w;
        As[a_c + 4][a_r] = av1.x;  As[a_c + 5][a_r] = av1.y;
        As[a_c + 6][a_r] = av1.z;  As[a_c + 7][a_r] = av1.w;
        const float* brow = Wqkv + (size_t)(k0 + b_r) * 768 + n0 + b_c;
        *(float4*)&Bs[b_r][b_c]     = *(const float4*)(brow);
        *(float4*)&Bs[b_r][b_c + 4] = *(const float4*)(brow + 4);
        __syncthreads();

        #pragma unroll
        for (int kk = 0; kk < 16; kk++) {
            ulonglong2 a01 = *(const ulonglong2*)&As[kk][i0];
            ulonglong2 a23 = *(const ulonglong2*)&As[kk][i0 + 4];
            float4 bq0 = *(const float4*)&Bs[kk][j0];
            float4 bq1 = *(const float4*)&Bs[kk][j0 + 4];
            u64 bd[8];
            bd[0] = pack2(bq0.x, bq0.x); bd[1] = pack2(bq0.y, bq0.y);
            bd[2] = pack2(bq0.z, bq0.z); bd[3] = pack2(bq0.w, bq0.w);
            bd[4] = pack2(bq1.x, bq1.x); bd[5] = pack2(bq1.y, bq1.y);
            bd[6] = pack2(bq1.z, bq1.z); bd[7] = pack2(bq1.w, bq1.w);
            #pragma unroll
            for (int j = 0; j < 8; j++) {
                fma2(acc[0][j], a01.x, bd[j]);
                fma2(acc[1][j], a01.y, bd[j]);
                fma2(acc[2][j], a23.x, bd[j]);
                fma2(acc[3][j], a23.y, bd[j]);
            }
        }
        __syncthreads();
    }

    // ---- epilogue: bias + scatter into q/k/v [w][h][t][d]
    const int jg0 = n0 + j0;
    const int s   = jg0 >> 8;                       // 0=q,1=k,2=v
    float* dst = (s == 0) ? g_q : ((s == 1) ? g_k : g_v);
    const int rem = jg0 & 255;
    const int h   = rem >> 5;
    const int d0  = rem & 31;
    float bias[8];
    *(float4*)(bias)     = *(const float4*)(bqkv + jg0);
    *(float4*)(bias + 4) = *(const float4*)(bqkv + jg0 + 4);

    #pragma unroll
    for (int i2 = 0; i2 < 4; i2++) {
        float lo[8], hi[8];
        #pragma unroll
        for (int j = 0; j < 8; j++) unpack2(acc[i2][j], lo[j], hi[j]);
        #pragma unroll
        for (int half = 0; half < 2; half++) {
            const float* vals = half ? hi : lo;
            const int r = bx * 128 + i0 + 2 * i2 + half;
            const int w = r >> 6, t = r & 63;
            float* p = dst + (((size_t)(w * NH + h) * NW + t) << 5) + d0;
            float4 o0 = make_float4(vals[0] + bias[0], vals[1] + bias[1],
                                    vals[2] + bias[2], vals[3] + bias[3]);
            float4 o1 = make_float4(vals[4] + bias[4], vals[5] + bias[5],
                                    vals[6] + bias[6], vals[7] + bias[7]);
            *(float4*)(p)     = o0;
            *(float4*)(p + 4) = o1;
        }
    }
}

// =================================================================================
// Kernel 2: per-(window,head) attention. 64 threads.
//   Compression as 4x4 outer-product microtiles; softmax fully vectorized f32x2.
// =================================================================================
__global__ void __launch_bounds__(64) attn_kernel(const float* __restrict__ E_k,
                                                  const float* __restrict__ E_v,
                                                  const float* __restrict__ k_bank,
                                                  const float* __restrict__ v_bank)
{
    __shared__ __align__(16) float sKV[NW * HD];   // 64x32 raw k (then v)
    __shared__ __align__(16) float sE [NW * LK];   // 64x32 E_k (then E_v)
    __shared__ __align__(16) float sKc[NKEY * HD]; // 48x32
    __shared__ __align__(16) float sVc[NKEY * HD];

    const int blk = blockIdx.x;
    const int w   = blk >> 3;
    const int h   = blk & 7;
    const int tid = threadIdx.x;       // 0..63
    const size_t base = (size_t)blk * NW * HD;

    const int lg = tid >> 3, dg = tid & 7;   // compression tile ids
    const int l0 = lg * 4,   d0 = dg * 4;

    for (int sel = 0; sel < 2; sel++) {
        const float* src  = sel ? g_v : g_k;
        const float* E    = sel ? E_v : E_k;
        const float* bank = sel ? v_bank : k_bank;
        float* dstc       = sel ? sVc : sKc;

        // stage raw tile + E
        {
            const float4* sp = (const float4*)(src + base + tid * HD);
            float4* dp = (float4*)(sKV + tid * HD);
            #pragma unroll
            for (int i = 0; i < 8; i++) dp[i] = sp[i];
            const float4* ep = (const float4*)(E) + tid * 8;
            float4* ed = (float4*)(sE) + tid * 8;
            #pragma unroll
            for (int i = 0; i < 8; i++) ed[i] = ep[i];
        }
        __syncthreads();

        // compression: acc[li][pair] over 4 l-rows x 4 d-cols
        u64 acc[4][2] = {};
        #pragma unroll 4
        for (int nn = 0; nn < NW; nn++) {
            float4 e4 = *(const float4*)&sE[nn * LK + l0];
            ulonglong2 k2 = *(const ulonglong2*)&sKV[nn * HD + d0];
            u64 e0 = pack2(e4.x, e4.x), e1 = pack2(e4.y, e4.y);
            u64 e2 = pack2(e4.z, e4.z), e3 = pack2(e4.w, e4.w);
            fma2(acc[0][0], e0, k2.x); fma2(acc[0][1], e0, k2.y);
            fma2(acc[1][0], e1, k2.x); fma2(acc[1][1], e1, k2.y);
            fma2(acc[2][0], e2, k2.x); fma2(acc[2][1], e2, k2.y);
            fma2(acc[3][0], e3, k2.x); fma2(acc[3][1], e3, k2.y);
        }
        #pragma unroll
        for (int li = 0; li < 4; li++) {
            float f0, f1, f2, f3;
            unpack2(acc[li][0], f0, f1);
            unpack2(acc[li][1], f2, f3);
            *(float4*)&dstc[(l0 + li) * HD + d0] = make_float4(f0, f1, f2, f3);
        }
        // bank rows
        #pragma unroll
        for (int i = 0; i < 8; i++) {
            const int idx = tid + i * 64;
            const int g = idx >> 5, d = idx & 31;
            dstc[LK * HD + idx] = __ldg(bank + g * CDIM + h * HD + d);
        }
        __syncthreads();
    }

    // ---------- attention for query token = tid ----------
    u64 qr[16];
    {
        const ulonglong2* qp = (const ulonglong2*)(g_q + base + tid * HD);
        #pragma unroll
        for (int u = 0; u < 8; u++) {
            ulonglong2 v2 = qp[u];
            qr[2 * u] = v2.x; qr[2 * u + 1] = v2.y;
        }
    }

    const float scale = 0.17677669529663687f;   // 1/sqrt(32)
    u64 out2[16] = {};
    float denom = 0.f;

    for (int j = 0; j < NKEY; j++) {
        const ulonglong2* kp = (const ulonglong2*)&sKc[j * HD];
        u64 s2a = 0, s2b = 0;
        #pragma unroll
        for (int u = 0; u < 8; u++) {
            ulonglong2 kv = kp[u];
            fma2(s2a, qr[2 * u],     kv.x);
            fma2(s2b, qr[2 * u + 1], kv.y);
        }
        float a0, a1, b0, b1;
        unpack2(s2a, a0, a1);
        unpack2(s2b, b0, b1);
        const float sc = (a0 + a1) + (b0 + b1);
        const float e  = __expf(sc * scale);
        denom += e;
        const u64 e2 = pack2(e, e);
        const ulonglong2* vp = (const ulonglong2*)&sVc[j * HD];
        #pragma unroll
        for (int u = 0; u < 8; u++) {
            ulonglong2 vv = vp[u];
            fma2(out2[2 * u],     e2, vv.x);
            fma2(out2[2 * u + 1], e2, vv.y);
        }
    }
    const float inv = 1.f / denom;

    float* drow = g_ao + ((size_t)(w * NW + tid)) * CDIM + h * HD;
    #pragma unroll
    for (int p = 0; p < 8; p++) {
        float a, b, c, d;
        unpack2(out2[2 * p],     a, b);
        unpack2(out2[2 * p + 1], c, d);
        *(float4*)(drow + p * 4) = make_float4(a * inv, b * inv, c * inv, d * inv);
    }
}

// =================================================================================
// Kernel 3: projection GEMM fused with window-reverse scatter + bias.
//   Same tiling as qkv. M=65536 (window-major), K=256, N=256.
// =================================================================================
__global__ void __launch_bounds__(256) proj_kernel(const float* __restrict__ Wp,
                                                   const float* __restrict__ bp,
                                                   float* __restrict__ out)
{
    __shared__ __align__(16) float As[16][128];
    __shared__ __align__(16) float Bs[16][128];

    const int tid = threadIdx.x;
    const int bx  = blockIdx.x;
    const int n0  = blockIdx.y * 128;

    const int a_r = tid >> 1;
    const int a_c = (tid & 1) * 8;
    const float* arow = g_ao + (size_t)(bx * 128 + a_r) * CDIM;

    const int b_r = tid >> 4;
    const int b_c = (tid & 15) * 8;

    const int ty = tid >> 4, tx = tid & 15;
    const int i0 = ty * 8, j0 = tx * 8;

    u64 acc[4][8] = {};

    for (int k0 = 0; k0 < CDIM; k0 += 16) {
        float4 av0 = *(const float4*)(arow + k0 + a_c);
        float4 av1 = *(const float4*)(arow + k0 + a_c + 4);
        As[a_c + 0][a_r] = av0.x;  As[a_c + 1][a_r] = av0.y;
        As[a_c + 2][a_r] = av0.z;  As[a_c + 3][a_r] = av0.w;
        As[a_c + 4][a_r] = av1.x;  As[a_c + 5][a_r] = av1.y;
        As[a_c + 6][a_r] = av1.z;  As[a_c + 7][a_r] = av1.w;
        const float* brow = Wp + (size_t)(k0 + b_r) * CDIM + n0 + b_c;
        *(float4*)&Bs[b_r][b_c]     = *(const float4*)(brow);
        *(float4*)&Bs[b_r][b_c + 4] = *(const float4*)(brow + 4);
        __syncthreads();

        #pragma unroll
        for (int kk = 0; kk < 16; kk++) {
            ulonglong2 a01 = *(const ulonglong2*)&As[kk][i0];
            ulonglong2 a23 = *(const ulonglong2*)&As[kk][i0 + 4];
            float4 bq0 = *(const float4*)&Bs[kk][j0];
            float4 bq1 = *(const float4*)&Bs[kk][j0 + 4];
            u64 bd[8];
            bd[0] = pack2(bq0.x, bq0.x); bd[1] = pack2(bq0.y, bq0.y);
            bd[2] = pack2(bq0.z, bq0.z); bd[3] = pack2(bq0.w, bq0.w);
            bd[4] = pack2(bq1.x, bq1.x); bd[5] = pack2(bq1.y, bq1.y);
            bd[6] = pack2(bq1.z, bq1.z); bd[7] = pack2(bq1.w, bq1.w);
            #pragma unroll
            for (int j = 0; j < 8; j++) {
                fma2(acc[0][j], a01.x, bd[j]);
                fma2(acc[1][j], a01.y, bd[j]);
                fma2(acc[2][j], a23.x, bd[j]);
                fma2(acc[3][j], a23.y, bd[j]);
            }
        }
        __syncthreads();
    }

    const int jg0 = n0 + j0;
    float bias[8];
    *(float4*)(bias)     = *(const float4*)(bp + jg0);
    *(float4*)(bias + 4) = *(const float4*)(bp + jg0 + 4);

    #pragma unroll
    for (int i2 = 0; i2 < 4; i2++) {
        float lo[8], hi[8];
        #pragma unroll
        for (int j = 0; j < 8; j++) unpack2(acc[i2][j], lo[j], hi[j]);
        #pragma unroll
        for (int half = 0; half < 2; half++) {
            const float* vals = half ? hi : lo;
            const int r = bx * 128 + i0 + 2 * i2 + half;
            const int w = r >> 6, t = r & 63;
            const int b = w >> 6;
            const int wrem = w & 63;
            const int gtok = (((wrem >> 3) * 8 + (t >> 3)) << 6) + ((wrem & 7) * 8 + (t & 7));
            float* p = out + (size_t)(b * NTOK + gtok) * CDIM + jg0;
            float4 o0 = make_float4(vals[0] + bias[0], vals[1] + bias[1],
                                    vals[2] + bias[2], vals[3] + bias[3]);
            float4 o1 = make_float4(vals[4] + bias[4], vals[5] + bias[5],
                                    vals[6] + bias[6], vals[7] + bias[7]);
            *(float4*)(p)     = o0;
            *(float4*)(p + 4) = o1;
        }
    }
}

// =================================================================================
extern "C" void kernel_launch(void* const* d_in, const int* in_sizes, int n_in,
                              void* d_out, int out_size)
{
    (void)in_sizes; (void)n_in; (void)out_size;
    const float* x     = (const float*)d_in[0];
    const float* Wqkv  = (const float*)d_in[1];
    const float* bqkv  = (const float*)d_in[2];
    const float* E_k   = (const float*)d_in[3];
    const float* E_v   = (const float*)d_in[4];
    const float* kbank = (const float*)d_in[5];
    const float* vbank = (const float*)d_in[6];
    const float* Wp    = (const float*)d_in[7];
    const float* bp    = (const float*)d_in[8];
    float* out = (float*)d_out;

    qkv_kernel<<<dim3(MROWS / 128, 6), 256>>>(x, Wqkv, bqkv);
    attn_kernel<<<BW * NH, 64>>>(E_k, E_v, kbank, vbank);
    proj_kernel<<<dim3(MROWS / 128, 2), 256>>>(Wp, bp, out);
}

// round 5
// speedup vs baseline: 2.3027x; 1.8327x over previous
#include <cuda_runtime.h>
#include <cuda_bf16.h>
#include <cstdint>

// ---------------- problem constants ----------------
#define NTOK    4096
#define CDIM    256
#define NH      8
#define HD      32
#define LK      32
#define GB      16
#define NW      64
#define BW      1024
#define MROWS   65536
#define NKEY    48

typedef unsigned long long u64;
typedef __nv_bfloat16 bf16;

// ---------------- device-global scratch ----------------
__device__ __align__(16) float g_q[BW * NH * NW * HD];
__device__ __align__(16) float g_k[BW * NH * NW * HD];
__device__ __align__(16) float g_v[BW * NH * NW * HD];
__device__ __align__(16) bf16  g_xhi[(size_t)MROWS * CDIM];
__device__ __align__(16) bf16  g_xlo[(size_t)MROWS * CDIM];
__device__ __align__(16) bf16  g_aohi[(size_t)MROWS * CDIM];
__device__ __align__(16) bf16  g_aolo[(size_t)MROWS * CDIM];
__device__ __align__(16) bf16  g_wqkvT_hi[768 * 256];
__device__ __align__(16) bf16  g_wqkvT_lo[768 * 256];
__device__ __align__(16) bf16  g_wpT_hi[256 * 256];
__device__ __align__(16) bf16  g_wpT_lo[256 * 256];

// ---------------- helpers ----------------
__device__ __forceinline__ uint32_t smem_u32(const void* p) {
    uint32_t a;
    asm("{ .reg .u64 t; cvta.to.shared.u64 t, %1; cvt.u32.u64 %0, t; }" : "=r"(a) : "l"(p));
    return a;
}
__device__ __forceinline__ u64 pack2(float lo, float hi) {
    u64 d;
    asm("mov.b64 %0, {%1, %2};" : "=l"(d)
        : "r"(__float_as_uint(lo)), "r"(__float_as_uint(hi)));
    return d;
}
__device__ __forceinline__ void unpack2(u64 v, float& lo, float& hi) {
    unsigned int a, b;
    asm("mov.b64 {%0, %1}, %2;" : "=r"(a), "=r"(b) : "l"(v));
    lo = __uint_as_float(a); hi = __uint_as_float(b);
}
__device__ __forceinline__ void fma2(u64& acc, u64 a, u64 b) {
    asm("fma.rn.f32x2 %0, %1, %2, %0;" : "+l"(acc) : "l"(a), "l"(b));
}

__device__ __forceinline__ void cp16(uint32_t saddr, const void* gaddr) {
    asm volatile("cp.async.cg.shared.global [%0], [%1], 16;"
                 :: "r"(saddr), "l"(gaddr));
}
#define CP_COMMIT() asm volatile("cp.async.commit_group;" ::: "memory")
#define CP_WAIT(n)  asm volatile("cp.async.wait_group %0;" :: "n"(n) : "memory")

__device__ __forceinline__ void ldsm4(uint32_t (&r)[4], uint32_t addr) {
    asm volatile("ldmatrix.sync.aligned.m8n8.x4.shared.b16 {%0,%1,%2,%3}, [%4];"
                 : "=r"(r[0]), "=r"(r[1]), "=r"(r[2]), "=r"(r[3]) : "r"(addr));
}
__device__ __forceinline__ void mma16816(float (&d)[4], const uint32_t (&a)[4],
                                         uint32_t b0, uint32_t b1) {
    asm volatile("mma.sync.aligned.m16n8k16.row.col.f32.bf16.bf16.f32 "
                 "{%0,%1,%2,%3}, {%4,%5,%6,%7}, {%8,%9}, {%0,%1,%2,%3};"
                 : "+f"(d[0]), "+f"(d[1]), "+f"(d[2]), "+f"(d[3])
                 : "r"(a[0]), "r"(a[1]), "r"(a[2]), "r"(a[3]), "r"(b0), "r"(b1));
}

// =================================================================================
// conv_x: fp32 x -> window-gathered bf16 hi/lo rows [row][k]
// =================================================================================
__global__ void __launch_bounds__(256) conv_x(const float* __restrict__ x)
{
    const int t   = blockIdx.x * 256 + threadIdx.x;
    const int row = t >> 5;
    const int seg = (t & 31) * 8;
    const int w   = row >> 6, tt = row & 63;
    const int b   = w >> 6,  wrem = w & 63;
    const int gtok = (((wrem >> 3) * 8 + (tt >> 3)) << 6) + ((wrem & 7) * 8 + (tt & 7));
    const float* src = x + ((size_t)(b * NTOK + gtok)) * CDIM + seg;

    float v[8];
    *(float4*)(v)     = *(const float4*)(src);
    *(float4*)(v + 4) = *(const float4*)(src + 4);

    bf16 hs[8], ls[8];
    #pragma unroll
    for (int i = 0; i < 8; i++) {
        hs[i] = __float2bfloat16_rn(v[i]);
        ls[i] = __float2bfloat16_rn(v[i] - __bfloat162float(hs[i]));
    }
    *(uint4*)(g_xhi + (size_t)row * CDIM + seg) = *(uint4*)hs;
    *(uint4*)(g_xlo + (size_t)row * CDIM + seg) = *(uint4*)ls;
}

// =================================================================================
// conv_w: transpose + split W_qkv [256][768] and W_proj [256][256] into [n][k] hi/lo
// =================================================================================
__global__ void __launch_bounds__(64) conv_w(const float* __restrict__ Wqkv,
                                             const float* __restrict__ Wp)
{
    const int n = blockIdx.x;
    for (int k = threadIdx.x; k < CDIM; k += 64) {
        float val; bf16 *dh, *dl;
        if (n < 768) {
            val = Wqkv[(size_t)k * 768 + n];
            dh = g_wqkvT_hi + (size_t)n * CDIM + k;
            dl = g_wqkvT_lo + (size_t)n * CDIM + k;
        } else {
            const int n2 = n - 768;
            val = Wp[(size_t)k * CDIM + n2];
            dh = g_wpT_hi + (size_t)n2 * CDIM + k;
            dl = g_wpT_lo + (size_t)n2 * CDIM + k;
        }
        bf16 h = __float2bfloat16_rn(val);
        *dh = h;
        *dl = __float2bfloat16_rn(val - __bfloat162float(h));
    }
}

// =================================================================================
// HMMA bf16-split GEMM.  BM=128 BN=128 BK=32, 256 thr, warp tile 64x32.
//   smem row stride 80B (64B data + 16 pad) -> conflict-free ldmatrix.
//   MODE 0: qkv (grid (512,6), scatter->g_q/g_k/g_v + bias)
//   MODE 1: proj (grid (512,2), window-reverse->out + bias)
// =================================================================================
#define RS   80
#define AHI  0
#define ALO  10240
#define BHI  20480
#define BLO  30720
#define STG  40960
#define SMEMB (2 * STG)

template<int MODE>
__global__ void __launch_bounds__(256) hmma_gemm(const float* __restrict__ bias,
                                                 float* __restrict__ outp)
{
    extern __shared__ char sm[];
    const uint32_t smb = smem_u32(sm);
    const int tid  = threadIdx.x;
    const int lane = tid & 31, wid = tid >> 5;
    const int warp_m = wid >> 2, warp_n = wid & 3;      // 2 x 4 warps
    const int bx = blockIdx.x, by = blockIdx.y;

    const bf16* Ahi_g = (MODE == 0) ? g_xhi : g_aohi;
    const bf16* Alo_g = (MODE == 0) ? g_xlo : g_aolo;
    const bf16* Bhi_g = (MODE == 0) ? g_wqkvT_hi : g_wpT_hi;
    const bf16* Blo_g = (MODE == 0) ? g_wqkvT_lo : g_wpT_lo;

    const size_t a_base = (size_t)(bx * 128) * CDIM;
    const size_t b_base = (size_t)(by * 128) * CDIM;

    // ---- ldmatrix addresses (within-matrix offsets)
    const uint32_t a_frag = (uint32_t)((warp_m * 64 + (lane & 15)) * RS
                                       + (lane >> 4) * 16);
    const uint32_t b_frag = (uint32_t)((warp_n * 32 + (lane & 7) + ((lane >> 4) << 3)) * RS
                                       + ((lane >> 3) & 1) * 16);

    float acc[4][4][4] = {};

    // per-stage: 128 rows x 64B per matrix = 512 x 16B chunks; 256 threads x 2
    auto stage_load = [&](int s, int kt) {
        const uint32_t sb = smb + s * STG;
        #pragma unroll
        for (int i = 0; i < 2; i++) {
            const int c   = tid + i * 256;          // 0..511
            const int row = c >> 2;
            const int kc  = c & 3;
            const uint32_t so = (uint32_t)(row * RS + kc * 16);
            const size_t   go = (size_t)row * CDIM + (size_t)kt * 32 + kc * 8;
            cp16(sb + AHI + so, Ahi_g + a_base + go);
            cp16(sb + ALO + so, Alo_g + a_base + go);
            cp16(sb + BHI + so, Bhi_g + b_base + go);
            cp16(sb + BLO + so, Blo_g + b_base + go);
        }
    };

    stage_load(0, 0);
    CP_COMMIT();

    #pragma unroll 1
    for (int it = 0; it < 8; it++) {
        if (it < 7) { stage_load((it + 1) & 1, it + 1); CP_COMMIT(); CP_WAIT(1); }
        else        { CP_WAIT(0); }
        __syncthreads();

        const uint32_t st = smb + (it & 1) * STG;
        #pragma unroll
        for (int kk = 0; kk < 2; kk++) {
            uint32_t ahi[4][4], alo[4][4], bhi[4][2], blo[4][2];
            #pragma unroll
            for (int mt = 0; mt < 4; mt++) {
                ldsm4(ahi[mt], st + AHI + a_frag + mt * (16 * RS) + kk * 32);
                ldsm4(alo[mt], st + ALO + a_frag + mt * (16 * RS) + kk * 32);
            }
            #pragma unroll
            for (int np = 0; np < 2; np++) {
                uint32_t th[4], tl[4];
                ldsm4(th, st + BHI + b_frag + np * (16 * RS) + kk * 32);
                ldsm4(tl, st + BLO + b_frag + np * (16 * RS) + kk * 32);
                bhi[np * 2][0] = th[0]; bhi[np * 2][1] = th[1];
                bhi[np * 2 + 1][0] = th[2]; bhi[np * 2 + 1][1] = th[3];
                blo[np * 2][0] = tl[0]; blo[np * 2][1] = tl[1];
                blo[np * 2 + 1][0] = tl[2]; blo[np * 2 + 1][1] = tl[3];
            }
            #pragma unroll
            for (int mt = 0; mt < 4; mt++)
                #pragma unroll
                for (int nt = 0; nt < 4; nt++) {
                    mma16816(acc[mt][nt], ahi[mt], bhi[nt][0], bhi[nt][1]);
                    mma16816(acc[mt][nt], ahi[mt], blo[nt][0], blo[nt][1]);
                    mma16816(acc[mt][nt], alo[mt], bhi[nt][0], bhi[nt][1]);
                }
        }
        __syncthreads();
    }

    // ---------------- epilogue ----------------
    const int w = bx * 2 + warp_m;               // window id (64 rows per warp_m)
    const int qrow = lane >> 2;                  // 0..7
    const int qcol = (lane & 3) * 2;             // 0,2,4,6

    if (MODE == 0) {
        const int s  = by >> 1;
        float* dst = (s == 0) ? g_q : ((s == 1) ? g_k : g_v);
        const int h = (by & 1) * 4 + warp_n;
        float* hb = dst + (((size_t)(w * NH + h)) << 11);   // *NW*HD
        #pragma unroll
        for (int nt = 0; nt < 4; nt++) {
            const int d  = nt * 8 + qcol;
            const int jg = by * 128 + warp_n * 32 + d;
            const float2 b2 = *(const float2*)(bias + jg);
            #pragma unroll
            for (int mt = 0; mt < 4; mt++) {
                const int tok = mt * 16 + qrow;
                float2 o0 = make_float2(acc[mt][nt][0] + b2.x, acc[mt][nt][1] + b2.y);
                float2 o1 = make_float2(acc[mt][nt][2] + b2.x, acc[mt][nt][3] + b2.y);
                *(float2*)(hb + ((tok)     << 5) + d) = o0;
                *(float2*)(hb + ((tok + 8) << 5) + d) = o1;
            }
        }
    } else {
        const int b = w >> 6, wrem = w & 63;
        #pragma unroll
        for (int nt = 0; nt < 4; nt++) {
            const int jg = by * 128 + warp_n * 32 + nt * 8 + qcol;
            const float2 b2 = *(const float2*)(bias + jg);
            #pragma unroll
            for (int mt = 0; mt < 4; mt++) {
                #pragma unroll
                for (int half = 0; half < 2; half++) {
                    const int tok = mt * 16 + qrow + half * 8;
                    const int gtok = (((wrem >> 3) * 8 + (tok >> 3)) << 6)
                                   + ((wrem & 7) * 8 + (tok & 7));
                    float2 o = make_float2(acc[mt][nt][half * 2]     + b2.x,
                                           acc[mt][nt][half * 2 + 1] + b2.y);
                    *(float2*)(outp + ((size_t)(b * NTOK + gtok)) * CDIM + jg) = o;
                }
            }
        }
    }
}

// =================================================================================
// attn kernel: per-(window,head), 64 threads; outputs bf16 hi/lo for proj GEMM
// =================================================================================
__global__ void __launch_bounds__(64) attn_kernel(const float* __restrict__ E_k,
                                                  const float* __restrict__ E_v,
                                                  const float* __restrict__ k_bank,
                                                  const float* __restrict__ v_bank)
{
    __shared__ __align__(16) float sKV[NW * HD];
    __shared__ __align__(16) float sE [NW * LK];
    __shared__ __align__(16) float sKc[NKEY * HD];
    __shared__ __align__(16) float sVc[NKEY * HD];

    const int blk = blockIdx.x;
    const int w   = blk >> 3;
    const int h   = blk & 7;
    const int tid = threadIdx.x;
    const size_t base = (size_t)blk * NW * HD;

    const int lg = tid >> 3, dg = tid & 7;
    const int l0 = lg * 4,   d0 = dg * 4;

    for (int sel = 0; sel < 2; sel++) {
        const float* src  = sel ? g_v : g_k;
        const float* E    = sel ? E_v : E_k;
        const float* bank = sel ? v_bank : k_bank;
        float* dstc       = sel ? sVc : sKc;

        {
            const float4* sp = (const float4*)(src + base + tid * HD);
            float4* dp = (float4*)(sKV + tid * HD);
            #pragma unroll
            for (int i = 0; i < 8; i++) dp[i] = sp[i];
            const float4* ep = (const float4*)(E) + tid * 8;
            float4* ed = (float4*)(sE) + tid * 8;
            #pragma unroll
            for (int i = 0; i < 8; i++) ed[i] = ep[i];
        }
        __syncthreads();

        u64 acc[4][2] = {};
        #pragma unroll 4
        for (int nn = 0; nn < NW; nn++) {
            float4 e4 = *(const float4*)&sE[nn * LK + l0];
            ulonglong2 k2 = *(const ulonglong2*)&sKV[nn * HD + d0];
            u64 e0 = pack2(e4.x, e4.x), e1 = pack2(e4.y, e4.y);
            u64 e2 = pack2(e4.z, e4.z), e3 = pack2(e4.w, e4.w);
            fma2(acc[0][0], e0, k2.x); fma2(acc[0][1], e0, k2.y);
            fma2(acc[1][0], e1, k2.x); fma2(acc[1][1], e1, k2.y);
            fma2(acc[2][0], e2, k2.x); fma2(acc[2][1], e2, k2.y);
            fma2(acc[3][0], e3, k2.x); fma2(acc[3][1], e3, k2.y);
        }
        #pragma unroll
        for (int li = 0; li < 4; li++) {
            float f0, f1, f2, f3;
            unpack2(acc[li][0], f0, f1);
            unpack2(acc[li][1], f2, f3);
            *(float4*)&dstc[(l0 + li) * HD + d0] = make_float4(f0, f1, f2, f3);
        }
        #pragma unroll
        for (int i = 0; i < 8; i++) {
            const int idx = tid + i * 64;
            const int g = idx >> 5, d = idx & 31;
            dstc[LK * HD + idx] = __ldg(bank + g * CDIM + h * HD + d);
        }
        __syncthreads();
    }

    u64 qr[16];
    {
        const ulonglong2* qp = (const ulonglong2*)(g_q + base + tid * HD);
        #pragma unroll
        for (int u = 0; u < 8; u++) {
            ulonglong2 v2 = qp[u];
            qr[2 * u] = v2.x; qr[2 * u + 1] = v2.y;
        }
    }

    const float scale = 0.17677669529663687f;
    u64 out2[16] = {};
    float denom = 0.f;

    for (int j = 0; j < NKEY; j++) {
        const ulonglong2* kp = (const ulonglong2*)&sKc[j * HD];
        u64 s2a = 0, s2b = 0;
        #pragma unroll
        for (int u = 0; u < 8; u++) {
            ulonglong2 kv = kp[u];
            fma2(s2a, qr[2 * u],     kv.x);
            fma2(s2b, qr[2 * u + 1], kv.y);
        }
        float a0, a1, b0, b1;
        unpack2(s2a, a0, a1);
        unpack2(s2b, b0, b1);
        const float sc = (a0 + a1) + (b0 + b1);
        const float e  = __expf(sc * scale);
        denom += e;
        const u64 e2 = pack2(e, e);
        const ulonglong2* vp = (const ulonglong2*)&sVc[j * HD];
        #pragma unroll
        for (int u = 0; u < 8; u++) {
            ulonglong2 vv = vp[u];
            fma2(out2[2 * u],     e2, vv.x);
            fma2(out2[2 * u + 1], e2, vv.y);
        }
    }
    const float inv = 1.f / denom;

    const size_t rowoff = ((size_t)(w * NW + tid)) * CDIM + h * HD;
    #pragma unroll
    for (int p = 0; p < 4; p++) {
        float vv[8];
        unpack2(out2[4 * p],     vv[0], vv[1]);
        unpack2(out2[4 * p + 1], vv[2], vv[3]);
        unpack2(out2[4 * p + 2], vv[4], vv[5]);
        unpack2(out2[4 * p + 3], vv[6], vv[7]);
        bf16 hs[8], ls[8];
        #pragma unroll
        for (int i = 0; i < 8; i++) {
            const float f = vv[i] * inv;
            hs[i] = __float2bfloat16_rn(f);
            ls[i] = __float2bfloat16_rn(f - __bfloat162float(hs[i]));
        }
        *(uint4*)(g_aohi + rowoff + p * 8) = *(uint4*)hs;
        *(uint4*)(g_aolo + rowoff + p * 8) = *(uint4*)ls;
    }
}

// =================================================================================
extern "C" void kernel_launch(void* const* d_in, const int* in_sizes, int n_in,
                              void* d_out, int out_size)
{
    (void)in_sizes; (void)n_in; (void)out_size;
    const float* x     = (const float*)d_in[0];
    const float* Wqkv  = (const float*)d_in[1];
    const float* bqkv  = (const float*)d_in[2];
    const float* E_k   = (const float*)d_in[3];
    const float* E_v   = (const float*)d_in[4];
    const float* kbank = (const float*)d_in[5];
    const float* vbank = (const float*)d_in[6];
    const float* Wp    = (const float*)d_in[7];
    const float* bp    = (const float*)d_in[8];
    float* out = (float*)d_out;

    cudaFuncSetAttribute(hmma_gemm<0>,
                         cudaFuncAttributeMaxDynamicSharedMemorySize, SMEMB);
    cudaFuncSetAttribute(hmma_gemm<1>,
                         cudaFuncAttributeMaxDynamicSharedMemorySize, SMEMB);

    conv_x<<<8192, 256>>>(x);
    conv_w<<<1024, 64>>>(Wqkv, Wp);
    hmma_gemm<0><<<dim3(512, 6), 256, SMEMB>>>(bqkv, nullptr);
    attn_kernel<<<BW * NH, 64>>>(E_k, E_v, kbank, vbank);
    hmma_gemm<1><<<dim3(512, 2), 256, SMEMB>>>(bp, out);
}